// round 6
// baseline (speedup 1.0000x reference)
#include <cuda_runtime.h>
#include <math.h>

#define DD   128
#define NMAX 100000
#define EMAX 1600000
#define NG   64

// Scratch (static __device__ globals: allocation-free per harness rules)
__device__ __align__(16) float g_hs [(size_t)NMAX * DD];  // (x@W)*dis[row]
__device__ __align__(16) float g_agg[(size_t)NMAX * DD];  // scatter accumulator
__device__ __align__(16) float g_h  [(size_t)NMAX * DD];  // layer-1 output
__device__ __align__(16) float g_sums[NG * DD];
__device__ float g_dis[NMAX];
__device__ int   g_deg[NMAX];
__device__ float g_cnt[NG];

__device__ __forceinline__ void red4(float4* dst, float4 v) {
    asm volatile("red.global.add.v4.f32 [%0], {%1, %2, %3, %4};"
                 :: "l"(dst), "f"(v.x), "f"(v.y), "f"(v.z), "f"(v.w) : "memory");
}

__device__ __forceinline__ float lrelu(float v) { return v >= 0.f ? v : 0.01f * v; }

// ---------------------------------------------------------------- zero / deg
__global__ void k_zero_misc(int N) {
    int i = blockIdx.x * blockDim.x + threadIdx.x;
    if (i < N)       g_deg[i]  = 0;
    if (i < NG * DD) g_sums[i] = 0.f;
    if (i < NG)      g_cnt[i]  = 0.f;
}

__global__ void k_zero_agg(long n4) {
    long i = (long)blockIdx.x * blockDim.x + threadIdx.x;
    if (i < n4) ((float4*)g_agg)[i] = make_float4(0.f, 0.f, 0.f, 0.f);
}

// NOTE: JAX default x64-disabled => edge_index / batch are int32 on device.
__global__ void k_deg(const int* __restrict__ ei, int E) {
    int e = blockIdx.x * blockDim.x + threadIdx.x;
    if (e < E) atomicAdd(&g_deg[ei[(size_t)E + e]], 1);
}

__global__ void k_dis(int N) {
    int i = blockIdx.x * blockDim.x + threadIdx.x;
    if (i < N) g_dis[i] = rsqrtf(1.0f + (float)g_deg[i]);   // +1 self-loop
}

// ------------------------------------------------------ GEMM: OUT = (X@W)*dis
// Block: 256 threads, 64 rows x 128 cols tile. W (64KB) + X tile (32KB) in smem.
// Thread t: cols 4*(t&31)..+3, rows (t>>5)*8..+7. 32 fp32 accumulators.
__global__ void k_gemm_scale(const float* __restrict__ X, const float* __restrict__ W,
                             float* __restrict__ OUT, int N) {
    extern __shared__ float sm[];
    float4* Wsh4 = (float4*)sm;           // 128*128 floats = 4096 float4
    float*  Xsh  = sm + DD * DD;          // 64*128 floats
    float4* Xsh4 = (float4*)Xsh;
    const int t = threadIdx.x;

    const float4* W4 = (const float4*)W;
#pragma unroll
    for (int i = 0; i < 16; i++) Wsh4[t + 256 * i] = W4[t + 256 * i];

    const int row0 = blockIdx.x * 64;
    const float4* X4 = (const float4*)X;
#pragma unroll
    for (int i = 0; i < 8; i++) {
        int idx = t + 256 * i;                 // float4 index in 64x32 tile
        int r = row0 + (idx >> 5);
        float4 v = make_float4(0.f, 0.f, 0.f, 0.f);
        if (r < N) v = X4[(size_t)r * 32 + (idx & 31)];
        Xsh4[idx] = v;
    }
    __syncthreads();

    const int c4 = t & 31;
    const int rg = t >> 5;
    float4 acc[8];
#pragma unroll
    for (int i = 0; i < 8; i++) acc[i] = make_float4(0.f, 0.f, 0.f, 0.f);

#pragma unroll 8
    for (int k = 0; k < DD; k++) {
        float4 w = Wsh4[k * 32 + c4];
#pragma unroll
        for (int i = 0; i < 8; i++) {
            float xv = Xsh[(rg * 8 + i) * DD + k];
            acc[i].x = fmaf(xv, w.x, acc[i].x);
            acc[i].y = fmaf(xv, w.y, acc[i].y);
            acc[i].z = fmaf(xv, w.z, acc[i].z);
            acc[i].w = fmaf(xv, w.w, acc[i].w);
        }
    }

    float4* O4 = (float4*)OUT;
#pragma unroll
    for (int i = 0; i < 8; i++) {
        int r = row0 + rg * 8 + i;
        if (r < N) {
            float s = g_dis[r];
            float4 v = acc[i];
            v.x *= s; v.y *= s; v.z *= s; v.w *= s;
            O4[(size_t)r * 32 + c4] = v;
        }
    }
}

// ------------------------------------------------- scatter: agg[col] += hs[row]
// One warp per edge: each lane moves one float4 (512B/edge), red.v4 (no-return).
__global__ void k_scatter(const int* __restrict__ ei, int E) {
    const int gw   = (blockIdx.x * blockDim.x + threadIdx.x) >> 5;
    const int lane = threadIdx.x & 31;
    if (gw >= E) return;
    const int row = __ldg(&ei[gw]);                 // source
    const int col = __ldg(&ei[(size_t)E + gw]);     // target
    float4 v = ((const float4*)g_hs)[(size_t)row * 32 + lane];
    red4(((float4*)g_agg) + (size_t)col * 32 + lane, v);
}

// ---------------------------------------------- finish1: h = lrelu(dis*(agg+hs)+b)
__global__ void k_finish1(const float* __restrict__ b, int N) {
    int idx = blockIdx.x * blockDim.x + threadIdx.x;     // over N*32 float4s
    if (idx >= N * 32) return;
    int i = idx >> 5, c4 = idx & 31;
    float s = g_dis[i];
    float4 a  = ((const float4*)g_agg)[idx];
    float4 hv = ((const float4*)g_hs)[idx];
    float4 bb = __ldg(((const float4*)b) + c4);
    float4 r;
    r.x = lrelu(s * (a.x + hv.x) + bb.x);
    r.y = lrelu(s * (a.y + hv.y) + bb.y);
    r.z = lrelu(s * (a.z + hv.z) + bb.z);
    r.w = lrelu(s * (a.w + hv.w) + bb.w);
    ((float4*)g_h)[idx] = r;
}

// ---------------- finish2 + pool: sums[batch[i]] += lrelu(dis*(agg+hs)+b)
// batch is sorted -> accumulate runs of 16 consecutive nodes locally, rare red.v4.
__global__ void k_finish2_pool(const float* __restrict__ b,
                               const int* __restrict__ batch, int N) {
    const int c4  = threadIdx.x & 31;
    const int grp = blockIdx.x * (blockDim.x >> 5) + (threadIdx.x >> 5);
    int i0 = grp * 16;
    if (i0 >= N) return;
    int iend = min(i0 + 16, N);
    float4 bb = __ldg(((const float4*)b) + c4);
    float4 ls = make_float4(0.f, 0.f, 0.f, 0.f);
    int curb = -1;
    for (int i = i0; i < iend; i++) {
        int bg = __ldg(&batch[i]);
        if (bg != curb) {
            if (curb >= 0) red4(((float4*)g_sums) + curb * 32 + c4, ls);
            curb = bg;
            ls = make_float4(0.f, 0.f, 0.f, 0.f);
        }
        float s = g_dis[i];
        size_t idx = (size_t)i * 32 + c4;
        float4 a  = ((const float4*)g_agg)[idx];
        float4 hv = ((const float4*)g_hs)[idx];
        ls.x += lrelu(s * (a.x + hv.x) + bb.x);
        ls.y += lrelu(s * (a.y + hv.y) + bb.y);
        ls.z += lrelu(s * (a.z + hv.z) + bb.z);
        ls.w += lrelu(s * (a.w + hv.w) + bb.w);
    }
    if (curb >= 0) red4(((float4*)g_sums) + curb * 32 + c4, ls);
}

__global__ void k_counts(const int* __restrict__ batch, int N) {
    __shared__ float sc[NG];
    int t = threadIdx.x;
    if (t < NG) sc[t] = 0.f;
    __syncthreads();
    int i = blockIdx.x * blockDim.x + t;
    if (i < N) atomicAdd(&sc[batch[i]], 1.0f);
    __syncthreads();
    if (t < NG && sc[t] != 0.f) atomicAdd(&g_cnt[t], sc[t]);
}

// ------------------------------------------ out[g] = (sums[g]/cnt[g]) . fcW + fcb
__global__ void k_final(const float* __restrict__ fcW, const float* __restrict__ fcb,
                        float* __restrict__ out) {
    int g = blockIdx.x;        // 64 blocks
    int c = threadIdx.x;       // 128 threads
    float inv = 1.0f / fmaxf(g_cnt[g], 1.0f);
    float v = g_sums[g * DD + c] * inv * __ldg(&fcW[c]);
#pragma unroll
    for (int o = 16; o; o >>= 1) v += __shfl_down_sync(0xffffffffu, v, o);
    __shared__ float ws[4];
    if ((c & 31) == 0) ws[c >> 5] = v;
    __syncthreads();
    if (c == 0) out[g] = ws[0] + ws[1] + ws[2] + ws[3] + __ldg(&fcb[0]);
}

// ============================================================================
extern "C" void kernel_launch(void* const* d_in, const int* in_sizes, int n_in,
                              void* d_out, int out_size) {
    const float* x     = (const float*)d_in[0];
    const int*   ei    = (const int*)d_in[1];     // int32 (JAX x64 disabled)
    const int*   batch = (const int*)d_in[2];     // int32
    const float* W1    = (const float*)d_in[3];
    const float* b1    = (const float*)d_in[4];
    const float* W2    = (const float*)d_in[5];
    const float* b2    = (const float*)d_in[6];
    const float* fcW   = (const float*)d_in[7];
    const float* fcb   = (const float*)d_in[8];
    float* out = (float*)d_out;

    const int N = in_sizes[0] / DD;
    const int E = in_sizes[1] / 2;

    float *hs_p = nullptr, *h_p = nullptr;
    cudaGetSymbolAddress((void**)&hs_p, g_hs);
    cudaGetSymbolAddress((void**)&h_p,  g_h);

    const int SMEM = (DD * DD + 64 * DD) * (int)sizeof(float);   // 96KB
    cudaFuncSetAttribute(k_gemm_scale, cudaFuncAttributeMaxDynamicSharedMemorySize, SMEM);

    const int T = 256;
    const long n4 = (long)N * 32;
    const int gN   = (N + T - 1) / T;
    const int gE   = (E + T - 1) / T;
    const int gN4  = (int)((n4 + T - 1) / T);
    const int gGEMM = (N + 63) / 64;
    const int gSCAT = (E + 7) / 8;     // 8 edge-warps per 256-thread block

    // degrees + symmetric-norm factors
    k_zero_misc<<<gN, T>>>(N);
    k_deg<<<gE, T>>>(ei, E);
    k_dis<<<gN, T>>>(N);

    // ---- layer 1
    k_zero_agg<<<gN4, T>>>(n4);
    k_gemm_scale<<<gGEMM, T, SMEM>>>(x, W1, hs_p, N);
    k_scatter<<<gSCAT, T>>>(ei, E);
    k_finish1<<<gN4, T>>>(b1, N);

    // ---- layer 2
    k_zero_agg<<<gN4, T>>>(n4);
    k_gemm_scale<<<gGEMM, T, SMEM>>>(h_p, W2, hs_p, N);
    k_scatter<<<gSCAT, T>>>(ei, E);
    k_finish2_pool<<<(N + 127) / 128, T>>>(b2, batch, N);

    // ---- head
    k_counts<<<gN, T>>>(batch, N);
    k_final<<<NG, DD>>>(fcW, fcb, out);
}

// round 10
// speedup vs baseline: 1.5275x; 1.5275x over previous
#include <cuda_runtime.h>
#include <math.h>

#define DD   128
#define NMAX 100000
#define EMAX 1600000
#define NG   64
#define SCAN_B 1024
#define NBLK_MAX 128

// Scratch (static __device__ globals: allocation-free per harness rules)
__device__ __align__(16) float g_hs [(size_t)NMAX * DD];  // (x@W)*dis[row]
__device__ __align__(16) float g_h  [(size_t)NMAX * DD];  // layer-1 output
__device__ __align__(16) float g_sums[NG * DD];
__device__ float g_dis[NMAX];
__device__ float g_cnt[NG];
// CSR-by-target build
__device__ int g_degc  [NMAX];     // in-degree (histogram of col)
__device__ int g_start [NMAX];     // exclusive prefix of degc
__device__ int g_cursor[NMAX];     // running cursor for bucket scatter
__device__ int g_srow  [EMAX];     // source row ids, grouped by target
__device__ int g_blk   [NBLK_MAX];
__device__ int g_blkoff[NBLK_MAX];

__device__ __forceinline__ void red4(float4* dst, float4 v) {
    asm volatile("red.global.add.v4.f32 [%0], {%1, %2, %3, %4};"
                 :: "l"(dst), "f"(v.x), "f"(v.y), "f"(v.z), "f"(v.w) : "memory");
}
__device__ __forceinline__ void red1(float* dst, float v) {
    asm volatile("red.global.add.f32 [%0], %1;" :: "l"(dst), "f"(v) : "memory");
}
__device__ __forceinline__ float lrelu(float v) { return v >= 0.f ? v : 0.01f * v; }

// ---------------------------------------------------------------- zero / hist
__global__ void k_zero_misc(int N) {
    int i = blockIdx.x * blockDim.x + threadIdx.x;
    if (i < N)       g_degc[i] = 0;
    if (i < NG * DD) g_sums[i] = 0.f;
    if (i < NG)      g_cnt[i]  = 0.f;
}

__global__ void k_hist(const int* __restrict__ ei, int E) {
    int e = blockIdx.x * blockDim.x + threadIdx.x;
    if (e < E) atomicAdd(&g_degc[ei[(size_t)E + e]], 1);
}

__global__ void k_dis(int N) {
    int i = blockIdx.x * blockDim.x + threadIdx.x;
    if (i < N) g_dis[i] = rsqrtf(1.0f + (float)g_degc[i]);   // +1 self-loop
}

// -------------------------------------------------- 3-phase exclusive scan
__global__ void k_scan1(int N) {
    __shared__ int sh[SCAN_B];
    int t = threadIdx.x, idx = blockIdx.x * SCAN_B + t;
    int c = (idx < N) ? g_degc[idx] : 0;
    sh[t] = c;
    __syncthreads();
#pragma unroll
    for (int o = 1; o < SCAN_B; o <<= 1) {
        int add = (t >= o) ? sh[t - o] : 0;
        __syncthreads();
        sh[t] += add;
        __syncthreads();
    }
    if (idx < N) g_start[idx] = sh[t] - c;          // block-local exclusive
    if (t == SCAN_B - 1) g_blk[blockIdx.x] = sh[t]; // block total
}

// warp-parallel exclusive scan over <=128 block totals (4 chunks of 32)
__global__ void k_scan2(int nblk) {
    int lane = threadIdx.x;                          // 32 threads
    int run = 0;
#pragma unroll
    for (int base = 0; base < NBLK_MAX; base += 32) {
        int b = base + lane;
        int v = (b < nblk) ? g_blk[b] : 0;
        int s = v;
#pragma unroll
        for (int o = 1; o < 32; o <<= 1) {
            int u = __shfl_up_sync(0xffffffffu, s, o);
            if (lane >= o) s += u;
        }
        if (b < nblk) g_blkoff[b] = run + s - v;     // exclusive
        run += __shfl_sync(0xffffffffu, s, 31);
    }
}

__global__ void k_scan3(int N) {
    int idx = blockIdx.x * SCAN_B + threadIdx.x;
    if (idx < N) {
        int s = g_start[idx] + g_blkoff[blockIdx.x];
        g_start[idx]  = s;
        g_cursor[idx] = s;
    }
}

// bucket-scatter edges: group source ids by target
__global__ void k_sortedges(const int* __restrict__ ei, int E) {
    int e = blockIdx.x * blockDim.x + threadIdx.x;
    if (e >= E) return;
    int col = ei[(size_t)E + e];
    int pos = atomicAdd(&g_cursor[col], 1);
    g_srow[pos] = ei[e];
}

// ------------------------------------------------------ GEMM: OUT = (X@W)*dis
__global__ void k_gemm_scale(const float* __restrict__ X, const float* __restrict__ W,
                             float* __restrict__ OUT, int N) {
    extern __shared__ float sm[];
    float4* Wsh4 = (float4*)sm;           // 128*128 floats
    float*  Xsh  = sm + DD * DD;          // 64*128 floats
    float4* Xsh4 = (float4*)Xsh;
    const int t = threadIdx.x;

    const float4* W4 = (const float4*)W;
#pragma unroll
    for (int i = 0; i < 16; i++) Wsh4[t + 256 * i] = W4[t + 256 * i];

    const int row0 = blockIdx.x * 64;
    const float4* X4 = (const float4*)X;
#pragma unroll
    for (int i = 0; i < 8; i++) {
        int idx = t + 256 * i;
        int r = row0 + (idx >> 5);
        float4 v = make_float4(0.f, 0.f, 0.f, 0.f);
        if (r < N) v = X4[(size_t)r * 32 + (idx & 31)];
        Xsh4[idx] = v;
    }
    __syncthreads();

    const int c4 = t & 31;
    const int rg = t >> 5;
    float4 acc[8];
#pragma unroll
    for (int i = 0; i < 8; i++) acc[i] = make_float4(0.f, 0.f, 0.f, 0.f);

#pragma unroll 8
    for (int k = 0; k < DD; k++) {
        float4 w = Wsh4[k * 32 + c4];
#pragma unroll
        for (int i = 0; i < 8; i++) {
            float xv = Xsh[(rg * 8 + i) * DD + k];
            acc[i].x = fmaf(xv, w.x, acc[i].x);
            acc[i].y = fmaf(xv, w.y, acc[i].y);
            acc[i].z = fmaf(xv, w.z, acc[i].z);
            acc[i].w = fmaf(xv, w.w, acc[i].w);
        }
    }

    float4* O4 = (float4*)OUT;
#pragma unroll
    for (int i = 0; i < 8; i++) {
        int r = row0 + rg * 8 + i;
        if (r < N) {
            float s = g_dis[r];
            float4 v = acc[i];
            v.x *= s; v.y *= s; v.z *= s; v.w *= s;
            O4[(size_t)r * 32 + c4] = v;
        }
    }
}

// -------- shared CSR aggregate body: returns finished node vector (pre-pool)
__device__ __forceinline__ float4 agg_node(int node, int lane, const float* __restrict__ b) {
    const float4* hs4 = (const float4*)g_hs;
    float4 acc = hs4[(size_t)node * 32 + lane];     // self-loop (pre-scaled)
    int e = g_start[node], end = e + g_degc[node];
    // 8-wide unrolled gather: maximize outstanding L2 loads per warp
    for (; e + 8 <= end; e += 8) {
        int r0 = __ldg(&g_srow[e+0]), r1 = __ldg(&g_srow[e+1]);
        int r2 = __ldg(&g_srow[e+2]), r3 = __ldg(&g_srow[e+3]);
        int r4 = __ldg(&g_srow[e+4]), r5 = __ldg(&g_srow[e+5]);
        int r6 = __ldg(&g_srow[e+6]), r7 = __ldg(&g_srow[e+7]);
        float4 v0 = hs4[(size_t)r0 * 32 + lane];
        float4 v1 = hs4[(size_t)r1 * 32 + lane];
        float4 v2 = hs4[(size_t)r2 * 32 + lane];
        float4 v3 = hs4[(size_t)r3 * 32 + lane];
        float4 v4 = hs4[(size_t)r4 * 32 + lane];
        float4 v5 = hs4[(size_t)r5 * 32 + lane];
        float4 v6 = hs4[(size_t)r6 * 32 + lane];
        float4 v7 = hs4[(size_t)r7 * 32 + lane];
        acc.x += ((v0.x + v1.x) + (v2.x + v3.x)) + ((v4.x + v5.x) + (v6.x + v7.x));
        acc.y += ((v0.y + v1.y) + (v2.y + v3.y)) + ((v4.y + v5.y) + (v6.y + v7.y));
        acc.z += ((v0.z + v1.z) + (v2.z + v3.z)) + ((v4.z + v5.z) + (v6.z + v7.z));
        acc.w += ((v0.w + v1.w) + (v2.w + v3.w)) + ((v4.w + v5.w) + (v6.w + v7.w));
    }
    for (; e < end; e++) {
        float4 v = hs4[(size_t)__ldg(&g_srow[e]) * 32 + lane];
        acc.x += v.x; acc.y += v.y; acc.z += v.z; acc.w += v.w;
    }
    const float s = g_dis[node];
    float4 bb = __ldg(((const float4*)b) + lane);
    float4 r;
    r.x = lrelu(fmaf(s, acc.x, bb.x));
    r.y = lrelu(fmaf(s, acc.y, bb.y));
    r.z = lrelu(fmaf(s, acc.z, bb.z));
    r.w = lrelu(fmaf(s, acc.w, bb.w));
    return r;
}

// ----------------------- layer 1: warp/node CSR aggregate + finish, fused
__global__ void k_agg1(const float* __restrict__ b, int N) {
    const int lane = threadIdx.x & 31;
    const int node = blockIdx.x * 8 + (threadIdx.x >> 5);
    if (node >= N) return;
    float4 r = agg_node(node, lane, b);
    ((float4*)g_h)[(size_t)node * 32 + lane] = r;
}

// -------- layer 2: CSR aggregate + finish + mean-pool partials, fused
__global__ void k_agg2_pool(const float* __restrict__ b,
                            const int* __restrict__ batch, int N) {
    const int lane = threadIdx.x & 31;
    const int node = blockIdx.x * 8 + (threadIdx.x >> 5);
    if (node >= N) return;
    float4 r = agg_node(node, lane, b);
    const int bg = __ldg(&batch[node]);
    red4(((float4*)g_sums) + bg * 32 + lane, r);
    if (lane == 0) red1(&g_cnt[bg], 1.0f);
}

// ------------------------------------------ out[g] = (sums[g]/cnt[g]) . fcW + fcb
__global__ void k_final(const float* __restrict__ fcW, const float* __restrict__ fcb,
                        float* __restrict__ out) {
    int g = blockIdx.x;
    int c = threadIdx.x;
    float inv = 1.0f / fmaxf(g_cnt[g], 1.0f);
    float v = g_sums[g * DD + c] * inv * __ldg(&fcW[c]);
#pragma unroll
    for (int o = 16; o; o >>= 1) v += __shfl_down_sync(0xffffffffu, v, o);
    __shared__ float ws[4];
    if ((c & 31) == 0) ws[c >> 5] = v;
    __syncthreads();
    if (c == 0) out[g] = ws[0] + ws[1] + ws[2] + ws[3] + __ldg(&fcb[0]);
}

// ============================================================================
extern "C" void kernel_launch(void* const* d_in, const int* in_sizes, int n_in,
                              void* d_out, int out_size) {
    const float* x     = (const float*)d_in[0];
    const int*   ei    = (const int*)d_in[1];     // int32 (JAX x64 disabled)
    const int*   batch = (const int*)d_in[2];     // int32
    const float* W1    = (const float*)d_in[3];
    const float* b1    = (const float*)d_in[4];
    const float* W2    = (const float*)d_in[5];
    const float* b2    = (const float*)d_in[6];
    const float* fcW   = (const float*)d_in[7];
    const float* fcb   = (const float*)d_in[8];
    float* out = (float*)d_out;

    const int N = in_sizes[0] / DD;
    const int E = in_sizes[1] / 2;

    float *hs_p = nullptr, *h_p = nullptr;
    cudaGetSymbolAddress((void**)&hs_p, g_hs);
    cudaGetSymbolAddress((void**)&h_p,  g_h);

    const int SMEM = (DD * DD + 64 * DD) * (int)sizeof(float);   // 96KB
    cudaFuncSetAttribute(k_gemm_scale, cudaFuncAttributeMaxDynamicSharedMemorySize, SMEM);

    const int T = 256;
    const int gN    = (N + T - 1) / T;
    const int gE    = (E + T - 1) / T;
    const int gGEMM = (N + 63) / 64;
    const int gAGG  = (N + 7) / 8;       // 8 node-warps per 256-thread block
    const int nblk  = (N + SCAN_B - 1) / SCAN_B;

    // CSR build (shared by both layers) + degree norm
    k_zero_misc<<<gN, T>>>(N);
    k_hist<<<gE, T>>>(ei, E);
    k_dis<<<gN, T>>>(N);
    k_scan1<<<nblk, SCAN_B>>>(N);
    k_scan2<<<1, 32>>>(nblk);
    k_scan3<<<nblk, SCAN_B>>>(N);
    k_sortedges<<<gE, T>>>(ei, E);

    // ---- layer 1
    k_gemm_scale<<<gGEMM, T, SMEM>>>(x, W1, hs_p, N);
    k_agg1<<<gAGG, T>>>(b1, N);

    // ---- layer 2
    k_gemm_scale<<<gGEMM, T, SMEM>>>(h_p, W2, hs_p, N);
    k_agg2_pool<<<gAGG, T>>>(b2, batch, N);

    // ---- head
    k_final<<<NG, DD>>>(fcW, fcb, out);
}